// round 12
// baseline (speedup 1.0000x reference)
#include <cuda_runtime.h>
#include <math.h>

#define NTHR   640
#define NW     (NTHR / 32)        // 20 warps
#define HID    512
#define TENC   16384
#define NVOCAB 31
#define MAXLEN 100
#define EOSI   29
#define PADV   30.0f
#define NBUF   3
#define MAXBLK 256
#define PCACHE 34                 // enc rows pinned in smem per block
#define LDSTRIDE 32               // 128B padding stride

// ---------------- device scratch ----------------
__device__ float g_ldot[NBUF][NVOCAB * LDSTRIDE];     // partial logit dots (summary part)
__device__ float g_tot[NBUF];                         // softmax denominators
__device__ __align__(16) float g_gh[2][3][HID];       // w_hh@h + b_hh (r,z,n), double buffered
__device__ __align__(16) float g_gx[NVOCAB][3 * HID]; // w_ih@embed[v] + b_ih
__device__ float g_lh[2][NVOCAB];                     // w_out[:,512:]@h + b_out, double buffered
__device__ volatile int g_arrive[MAXBLK * LDSTRIDE];  // 128B-padded arrive flags
__device__ volatile int g_release;

__device__ __forceinline__ float warp_allsum(float v) {
    #pragma unroll
    for (int o = 16; o; o >>= 1) v += __shfl_xor_sync(0xffffffffu, v, o);
    return v;
}
__device__ __forceinline__ int ld_acq(volatile int* p) {
    int v;
    asm volatile("ld.acquire.gpu.s32 %0, [%1];" : "=r"(v) : "l"((int*)p) : "memory");
    return v;
}
__device__ __forceinline__ void st_rel(volatile int* p, int v) {
    asm volatile("st.release.gpu.s32 [%0], %1;" :: "l"((int*)p), "r"(v) : "memory");
}
__device__ __forceinline__ int imin(int a, int b) { return a < b ? a : b; }
__device__ __forceinline__ int imax(int a, int b) { return a > b ? a : b; }

extern __shared__ float s_dyn[];   // [PCACHE*1024] enc rows | [31*512] w_out summary half

__global__ void __launch_bounds__(NTHR, 1)
decoder_kernel(const float* __restrict__ enc,     // [TENC, 1024] keys|values
               const float* __restrict__ embed,   // [31, 512]
               const float* __restrict__ w_ih,    // [1536, 512]
               const float* __restrict__ w_hh,    // [1536, 512]
               const float* __restrict__ b_ih,    // [1536]
               const float* __restrict__ b_hh,    // [1536]
               const float* __restrict__ w_out,   // [31, 1024]
               const float* __restrict__ b_out,   // [31]
               float* __restrict__ out)
{
    const int tid  = threadIdx.x;
    const int blk  = blockIdx.x;
    const int nblk = gridDim.x;
    const int wid  = tid >> 5;
    const int lane = tid & 31;
    const int base = lane * 4;

    float* s_enc   = s_dyn;                   // PCACHE rows of enc
    float* s_woutS = s_dyn + PCACHE * 1024;   // [31][512] summary-half of w_out

    __shared__ __align__(16) float s_hh[HID];          // h (per-block copy)
    __shared__ __align__(16) float s_sum[HID];         // block partial summary
    __shared__ __align__(16) float s_warp[8][HID];     // merge buffers
    __shared__ float s_exp[128];
    __shared__ unsigned s_mask[4];                     // per-row PAD masks (constant)
    __shared__ float s_red[NW];
    __shared__ float s_inv;
    __shared__ int   s_best;

    float* out_logits = out;                        // [100, 31]
    float* out_len    = out + MAXLEN * NVOCAB;      // [1]
    float* out_attn   = out + MAXLEN * NVOCAB + 1;  // [100, 16384]

    int ep = g_release;   // persistent epoch base

    // two-hop barrier: padded arrive flags -> block0 gather -> single release word
    auto grid_barrier = [&]() {
        ep++;
        __syncthreads();
        if (blk == 0) {
            if (tid == 0) st_rel(&g_arrive[0], ep);
            for (int i = tid; i < nblk; i += NTHR)
                if (i > 0) { while (ld_acq(&g_arrive[i * LDSTRIDE]) < ep) { } }
            __syncthreads();
            if (tid == 0) st_rel(&g_release, ep);
        } else {
            if (tid == 0) {
                st_rel(&g_arrive[blk * LDSTRIDE], ep);
                while (ld_acq(&g_release) < ep) { }
            }
        }
        __syncthreads();
    };

    // ---------------- per-launch init ----------------
    if (tid < HID) s_hh[tid] = 0.0f;      // h0 = 0
    if (tid == 0) s_best = EOSI;          // y0 = embed[EOS]
    if (tid < 4) s_mask[tid] = 0u;

    // row partition: gh-duty blocks (32..127) get w rows; others w+7(+1)
    const int nd  = nblk - 96;
    const int w   = (TENC - 7 * nd) / nblk;
    const int rem = TENC - 96 * w - nd * (w + 7);
    int t0, rows;
    if (blk < 32) {
        t0 = blk * (w + 7) + imin(blk, rem);
        rows = w + 7 + (blk < rem ? 1 : 0);
    } else if (blk < 128) {
        t0 = 32 * (w + 7) + imin(32, rem) + (blk - 32) * w;
        rows = w;
    } else {
        const int idx = blk - 128 + 32;
        t0 = 32 * (w + 7) + imin(32, rem) + 96 * w
           + (blk - 128) * (w + 7) + imax(0, imin(idx, rem) - 32);
        rows = w + 7 + (idx < rem ? 1 : 0);
    }
    const int t1 = t0 + rows;
    const int ts = t0 + PCACHE;           // stream start (rows > PCACHE always)

    // pin first PCACHE rows of our range into smem (once per launch)
    for (int i = tid; i < PCACHE * 1024; i += NTHR)
        s_enc[i] = __ldcg(enc + (size_t)t0 * 1024 + i);
    // w_out summary half -> smem
    for (int i = tid; i < NVOCAB * HID; i += NTHR)
        s_woutS[i] = w_out[(size_t)(i >> 9) * 1024 + (i & 511)];

    if (blk == 0) {
        if (tid < HID) {
            g_gh[0][0][tid] = b_hh[tid];
            g_gh[0][1][tid] = b_hh[tid + HID];
            g_gh[0][2][tid] = b_hh[tid + 2 * HID];
        }
        if (wid == 1 && lane < NVOCAB) {
            #pragma unroll
            for (int b = 0; b < NBUF; ++b) g_ldot[b][lane * LDSTRIDE] = 0.0f;
        }
        if (tid == 0) { g_tot[0] = 0.0f; g_tot[1] = 0.0f; g_tot[2] = 0.0f; }
    }
    // gx table: gx[v][u] = w_ih[u] . embed[v] + b_ih[u]
    {
        const int gw = blk * NW + wid;
        for (int r = gw; r < NVOCAB * 3 * HID; r += nblk * NW) {
            const int v = r / (3 * HID);
            const int u = r - v * (3 * HID);
            const float* wrow = w_ih + (size_t)u * HID;
            const float* erow = embed + (size_t)v * HID;
            float a = 0.0f;
            #pragma unroll
            for (int m = 0; m < 4; ++m) {
                int c = base + m * 128;
                float4 w4 = *(const float4*)(wrow + c);
                float4 e4 = *(const float4*)(erow + c);
                a = fmaf(w4.x, e4.x, fmaf(w4.y, e4.y, fmaf(w4.z, e4.z, fmaf(w4.w, e4.w, a))));
            }
            a = warp_allsum(a);
            if (lane == 0) g_gx[v][u] = a + b_ih[u];
        }
    }
    __syncthreads();
    // ---- precompute PAD masks (keys constant across steps) ----
    for (int t = t0 + wid; t < t1; t += NW) {
        const float* row = enc + (size_t)t * (2 * HID);
        float4 k0 = __ldcg((const float4*)(row + base));
        float4 k1 = __ldcg((const float4*)(row + base + 128));
        float4 k2 = __ldcg((const float4*)(row + base + 256));
        float4 k3 = __ldcg((const float4*)(row + base + 384));
        int ok = (k0.x != PADV) | (k0.y != PADV) | (k0.z != PADV) | (k0.w != PADV)
               | (k1.x != PADV) | (k1.y != PADV) | (k1.z != PADV) | (k1.w != PADV)
               | (k2.x != PADV) | (k2.y != PADV) | (k2.z != PADV) | (k2.w != PADV)
               | (k3.x != PADV) | (k3.y != PADV) | (k3.z != PADV) | (k3.w != PADV);
        ok = __any_sync(0xffffffffu, ok);
        if (lane == 0 && ok) atomicOr(&s_mask[(t - t0) >> 5], 1u << ((t - t0) & 31));
    }
    int eos_step = MAXLEN;

    grid_barrier();

    const float scale = 0.04419417382415922f;   // 1/sqrt(512)

    for (int k = 0; k <= MAXLEN; ++k) {
        // ============ Phase A: tiny epilogue of step k-1 (redundant per block) ============
        if (k > 0) {
            const int p  = (k - 1) % NBUF;
            const int pl = (k - 1) & 1;
            const float inv_total = 1.0f / g_tot[p];

            if (wid == 0) {
                float lg = -1e30f;
                if (lane < NVOCAB)
                    lg = g_ldot[p][lane * LDSTRIDE] * inv_total + g_lh[pl][lane];
                // shfl argmax, first-index tie-break
                unsigned kb = __float_as_uint(lg);
                kb = (kb & 0x80000000u) ? ~kb : (kb | 0x80000000u);
                unsigned long long pk = ((unsigned long long)kb << 6) | (unsigned)(63 - lane);
                #pragma unroll
                for (int o = 16; o; o >>= 1) {
                    unsigned long long q = __shfl_xor_sync(0xffffffffu, pk, o);
                    if (q > pk) pk = q;
                }
                if (lane == 0) {
                    int best = 63 - (int)(pk & 63u);
                    s_best = best;
                    if (blk == 0 && best == EOSI && eos_step == MAXLEN) eos_step = k - 1;
                }
                if (blk == 0 && lane < NVOCAB)
                    out_logits[(k - 1) * NVOCAB + lane] = lg;
            }
            // zero buffer (k+1)%3 (block 0, warp 1)
            if (blk == 0 && wid == 1) {
                const int zb = (k + 1) % NBUF;
                if (lane < NVOCAB) g_ldot[zb][lane * LDSTRIDE] = 0.0f;
                if (lane == 31) g_tot[zb] = 0.0f;
            }
            // attention output for step k-1
            for (int t = t0 + tid; t < t1; t += NTHR)
                out_attn[(size_t)(k - 1) * TENC + t] = s_exp[t - t0] * inv_total;
            __syncthreads();

            if (k == MAXLEN) break;

            // GRU pointwise: h^{(k)} = GRU(gx[best], gh, h^{(k-1)})
            if (tid < HID) {
                const int pg = k & 1;
                const float* gx = g_gx[s_best];
                float r = 1.0f / (1.0f + __expf(-(gx[tid]           + g_gh[pg][0][tid])));
                float z = 1.0f / (1.0f + __expf(-(gx[tid + HID]     + g_gh[pg][1][tid])));
                float n = tanhf(gx[tid + 2 * HID] + r * g_gh[pg][2][tid]);
                s_hh[tid] = (1.0f - z) * n + z * s_hh[tid];
            }
            __syncthreads();
        } else {
            if (tid < HID) {
                const float* gx = g_gx[EOSI];
                float r = 1.0f / (1.0f + __expf(-(gx[tid]           + g_gh[0][0][tid])));
                float z = 1.0f / (1.0f + __expf(-(gx[tid + HID]     + g_gh[0][1][tid])));
                float n = tanhf(gx[tid + 2 * HID] + r * g_gh[0][2][tid]);
                s_hh[tid] = (1.0f - z) * n;
            }
            __syncthreads();
        }

        // ============ Phase B: attention sweep ============
        float4 h0 = *(const float4*)(s_hh + base);
        float4 h1 = *(const float4*)(s_hh + base + 128);
        float4 h2 = *(const float4*)(s_hh + base + 256);
        float4 h3 = *(const float4*)(s_hh + base + 384);

        // lh duty: blocks 1..31, warp 0
        if (wid == 0 && blk >= 1 && blk <= NVOCAB) {
            const int v = blk - 1;
            const float* wrow = w_out + (size_t)v * 1024 + HID;
            float dot = 0.0f;
            float4 w4;
            w4 = *(const float4*)(wrow + base);
            dot = fmaf(w4.x, h0.x, fmaf(w4.y, h0.y, fmaf(w4.z, h0.z, fmaf(w4.w, h0.w, dot))));
            w4 = *(const float4*)(wrow + base + 128);
            dot = fmaf(w4.x, h1.x, fmaf(w4.y, h1.y, fmaf(w4.z, h1.z, fmaf(w4.w, h1.w, dot))));
            w4 = *(const float4*)(wrow + base + 256);
            dot = fmaf(w4.x, h2.x, fmaf(w4.y, h2.y, fmaf(w4.z, h2.z, fmaf(w4.w, h2.w, dot))));
            w4 = *(const float4*)(wrow + base + 384);
            dot = fmaf(w4.x, h3.x, fmaf(w4.y, h3.y, fmaf(w4.z, h3.z, fmaf(w4.w, h3.w, dot))));
            dot = warp_allsum(dot);
            if (lane == 0) g_lh[k & 1][v] = dot + b_out[v];
        }

        float4 acc0 = {0,0,0,0}, acc1 = {0,0,0,0}, acc2 = {0,0,0,0}, acc3 = {0,0,0,0};
        float esum = 0.0f;

        // ---- streamed rows: 1 row/iter, fused K+V float4, precomputed masks ----
        for (int t = ts + wid; t < t1; t += NW) {
            const float* row = enc + (size_t)t * (2 * HID);
            float4 k0 = __ldcg((const float4*)(row + base));
            float4 k1 = __ldcg((const float4*)(row + base + 128));
            float4 k2 = __ldcg((const float4*)(row + base + 256));
            float4 k3 = __ldcg((const float4*)(row + base + 384));
            float4 v0 = __ldcg((const float4*)(row + HID + base));
            float4 v1 = __ldcg((const float4*)(row + HID + base + 128));
            float4 v2 = __ldcg((const float4*)(row + HID + base + 256));
            float4 v3 = __ldcg((const float4*)(row + HID + base + 384));
            float p0 = k0.x*h0.x + k0.y*h0.y + k0.z*h0.z + k0.w*h0.w;
            float p1 = k1.x*h1.x + k1.y*h1.y + k1.z*h1.z + k1.w*h1.w;
            float p2 = k2.x*h2.x + k2.y*h2.y + k2.z*h2.z + k2.w*h2.w;
            float p3 = k3.x*h3.x + k3.y*h3.y + k3.z*h3.z + k3.w*h3.w;
            float d = (p0 + p1) + (p2 + p3);
            d = warp_allsum(d);
            const int it = t - t0;
            const unsigned m = (s_mask[it >> 5] >> (it & 31)) & 1u;
            float e = m ? __expf(d * scale) : 0.0f;
            if (lane == 0) { s_exp[it] = e; esum += e; }
            acc0.x = fmaf(e, v0.x, acc0.x); acc0.y = fmaf(e, v0.y, acc0.y);
            acc0.z = fmaf(e, v0.z, acc0.z); acc0.w = fmaf(e, v0.w, acc0.w);
            acc1.x = fmaf(e, v1.x, acc1.x); acc1.y = fmaf(e, v1.y, acc1.y);
            acc1.z = fmaf(e, v1.z, acc1.z); acc1.w = fmaf(e, v1.w, acc1.w);
            acc2.x = fmaf(e, v2.x, acc2.x); acc2.y = fmaf(e, v2.y, acc2.y);
            acc2.z = fmaf(e, v2.z, acc2.z); acc2.w = fmaf(e, v2.w, acc2.w);
            acc3.x = fmaf(e, v3.x, acc3.x); acc3.y = fmaf(e, v3.y, acc3.y);
            acc3.z = fmaf(e, v3.z, acc3.z); acc3.w = fmaf(e, v3.w, acc3.w);
        }

        // ---- pinned rows (smem) ----
        for (int t = t0 + wid; t < ts; t += NW) {
            const float* row = s_enc + (size_t)(t - t0) * (2 * HID);
            float4 k0 = *(const float4*)(row + base);
            float4 k1 = *(const float4*)(row + base + 128);
            float4 k2 = *(const float4*)(row + base + 256);
            float4 k3 = *(const float4*)(row + base + 384);
            float4 v0 = *(const float4*)(row + HID + base);
            float4 v1 = *(const float4*)(row + HID + base + 128);
            float4 v2 = *(const float4*)(row + HID + base + 256);
            float4 v3 = *(const float4*)(row + HID + base + 384);
            float p0 = k0.x*h0.x + k0.y*h0.y + k0.z*h0.z + k0.w*h0.w;
            float p1 = k1.x*h1.x + k1.y*h1.y + k1.z*h1.z + k1.w*h1.w;
            float p2 = k2.x*h2.x + k2.y*h2.y + k2.z*h2.z + k2.w*h2.w;
            float p3 = k3.x*h3.x + k3.y*h3.y + k3.z*h3.z + k3.w*h3.w;
            float d = (p0 + p1) + (p2 + p3);
            d = warp_allsum(d);
            const int it = t - t0;
            const unsigned m = (s_mask[it >> 5] >> (it & 31)) & 1u;
            float e = m ? __expf(d * scale) : 0.0f;
            if (lane == 0) { s_exp[it] = e; esum += e; }
            acc0.x = fmaf(e, v0.x, acc0.x); acc0.y = fmaf(e, v0.y, acc0.y);
            acc0.z = fmaf(e, v0.z, acc0.z); acc0.w = fmaf(e, v0.w, acc0.w);
            acc1.x = fmaf(e, v1.x, acc1.x); acc1.y = fmaf(e, v1.y, acc1.y);
            acc1.z = fmaf(e, v1.z, acc1.z); acc1.w = fmaf(e, v1.w, acc1.w);
            acc2.x = fmaf(e, v2.x, acc2.x); acc2.y = fmaf(e, v2.y, acc2.y);
            acc2.z = fmaf(e, v2.z, acc2.z); acc2.w = fmaf(e, v2.w, acc2.w);
            acc3.x = fmaf(e, v3.x, acc3.x); acc3.y = fmaf(e, v3.y, acc3.y);
            acc3.z = fmaf(e, v3.z, acc3.z); acc3.w = fmaf(e, v3.w, acc3.w);
        }

        // gh duty: blocks 32..108, one dot per warp, guard d<1536
        if (blk >= 32 && blk < 128) {
            const int d = (blk - 32) * NW + wid;
            if (d < 3 * HID) {
                const int g  = d >> 9;
                const int j  = d & 511;
                const int pn = (k + 1) & 1;
                const float* ur = w_hh + (size_t)(g * HID + j) * HID;
                float a = 0.0f;
                #pragma unroll
                for (int m = 0; m < 4; ++m) {
                    int c = base + m * 128;
                    float4 hx = *(const float4*)(s_hh + c);
                    float4 u4 = *(const float4*)(ur + c);
                    a = fmaf(hx.x, u4.x, fmaf(hx.y, u4.y, fmaf(hx.z, u4.z, fmaf(hx.w, u4.w, a))));
                }
                a = warp_allsum(a);
                if (lane == 0) g_gh[pn][g][j] = a + b_hh[g * HID + j];
            }
        }

        // ---- merge: 3-phase staging (8 buffers, 20 warps) ----
        if (lane == 0) s_red[wid] = esum;
        if (wid < 8) {
            *(float4*)&s_warp[wid][base]       = acc0;
            *(float4*)&s_warp[wid][base + 128] = acc1;
            *(float4*)&s_warp[wid][base + 256] = acc2;
            *(float4*)&s_warp[wid][base + 384] = acc3;
        }
        __syncthreads();
        if (wid >= 8 && wid < 16) {
            float* bdst = s_warp[wid - 8];
            float4 t;
            t = *(float4*)&bdst[base];
            t.x += acc0.x; t.y += acc0.y; t.z += acc0.z; t.w += acc0.w;
            *(float4*)&bdst[base] = t;
            t = *(float4*)&bdst[base + 128];
            t.x += acc1.x; t.y += acc1.y; t.z += acc1.z; t.w += acc1.w;
            *(float4*)&bdst[base + 128] = t;
            t = *(float4*)&bdst[base + 256];
            t.x += acc2.x; t.y += acc2.y; t.z += acc2.z; t.w += acc2.w;
            *(float4*)&bdst[base + 256] = t;
            t = *(float4*)&bdst[base + 384];
            t.x += acc3.x; t.y += acc3.y; t.z += acc3.z; t.w += acc3.w;
            *(float4*)&bdst[base + 384] = t;
        }
        __syncthreads();
        if (wid >= 16) {
            float* bdst = s_warp[wid - 16];
            float4 t;
            t = *(float4*)&bdst[base];
            t.x += acc0.x; t.y += acc0.y; t.z += acc0.z; t.w += acc0.w;
            *(float4*)&bdst[base] = t;
            t = *(float4*)&bdst[base + 128];
            t.x += acc1.x; t.y += acc1.y; t.z += acc1.z; t.w += acc1.w;
            *(float4*)&bdst[base + 128] = t;
            t = *(float4*)&bdst[base + 256];
            t.x += acc2.x; t.y += acc2.y; t.z += acc2.z; t.w += acc2.w;
            *(float4*)&bdst[base + 256] = t;
            t = *(float4*)&bdst[base + 384];
            t.x += acc3.x; t.y += acc3.y; t.z += acc3.z; t.w += acc3.w;
            *(float4*)&bdst[base + 384] = t;
        }
        __syncthreads();
        if (tid < HID) {
            float colsum = 0.0f;
            #pragma unroll
            for (int w8 = 0; w8 < 8; ++w8) colsum += s_warp[w8][tid];
            s_sum[tid] = colsum;
        }
        __syncthreads();

        // ---- partial logit dots: ldot[v] += w_outS[v] . s_sum (31 atomics/block) ----
        const int bb = k % NBUF;
        for (int v = wid; v < NVOCAB; v += NW) {
            const float* wrow = s_woutS + v * HID;
            float dot = 0.0f;
            #pragma unroll
            for (int m = 0; m < 4; ++m) {
                int c = base + m * 128;
                float4 w4 = *(const float4*)(wrow + c);
                float4 x4 = *(const float4*)(s_sum + c);
                dot = fmaf(w4.x, x4.x, fmaf(w4.y, x4.y, fmaf(w4.z, x4.z, fmaf(w4.w, x4.w, dot))));
            }
            dot = warp_allsum(dot);
            if (lane == 0) atomicAdd(&g_ldot[bb][v * LDSTRIDE], dot);
        }
        if (tid == 0) {
            float tot = 0.0f;
            #pragma unroll
            for (int w8 = 0; w8 < NW; ++w8) tot += s_red[w8];
            atomicAdd(&g_tot[bb], tot);
        }

        grid_barrier();   // the one barrier per step
    }

    if (blk == 0 && tid == 0) out_len[0] = (float)eos_step;
}

extern "C" void kernel_launch(void* const* d_in, const int* in_sizes, int n_in,
                              void* d_out, int out_size) {
    const float* enc   = (const float*)d_in[0];   // encoding [1,16384,1024]
    const float* embed = (const float*)d_in[2];
    const float* w_ih  = (const float*)d_in[3];
    const float* w_hh  = (const float*)d_in[4];
    const float* b_ih  = (const float*)d_in[5];
    const float* b_hh  = (const float*)d_in[6];
    const float* w_out = (const float*)d_in[7];
    const float* b_out = (const float*)d_in[8];
    (void)in_sizes; (void)n_in; (void)out_size;

    const int smem_dyn = (PCACHE * 1024 + NVOCAB * HID) * sizeof(float);   // 202752 B
    static int nblk = 0;
    if (!nblk) {
        cudaFuncSetAttribute(decoder_kernel,
                             cudaFuncAttributeMaxDynamicSharedMemorySize, smem_dyn);
        int dev = 0;
        cudaGetDevice(&dev);
        int sms = 0;
        cudaDeviceGetAttribute(&sms, cudaDevAttrMultiProcessorCount, dev);
        nblk = (sms >= 128 && sms <= MAXBLK) ? sms : 148;
    }
    decoder_kernel<<<nblk, NTHR, smem_dyn>>>(enc, embed, w_ih, w_hh, b_ih, b_hh,
                                             w_out, b_out, (float*)d_out);
}

// round 13
// speedup vs baseline: 1.0409x; 1.0409x over previous
#include <cuda_runtime.h>
#include <math.h>

#define NTHR   512
#define NW     (NTHR / 32)        // 16 warps
#define HID    512
#define TENC   16384
#define NVOCAB 31
#define MAXLEN 100
#define EOSI   29
#define PADV   30.0f
#define NBUF   3
#define MAXBLK 256
#define PCACHE 34                 // enc rows pinned in smem per block
#define LDSTRIDE 32               // 128B padding stride

// ---------------- device scratch ----------------
__device__ float g_ldot[NBUF][NVOCAB * LDSTRIDE];     // partial logit dots (summary part)
__device__ float g_tot[NBUF];                         // softmax denominators
__device__ __align__(16) float g_gh[2][3][HID];       // w_hh@h + b_hh (r,z,n), double buffered
__device__ __align__(16) float g_gx[NVOCAB][3 * HID]; // w_ih@embed[v] + b_ih
__device__ float g_lh[2][NVOCAB];                     // w_out[:,512:]@h + b_out, double buffered
__device__ volatile int g_arrive[MAXBLK * LDSTRIDE];  // 128B-padded arrive flags
__device__ volatile int g_release;

__device__ __forceinline__ float warp_allsum(float v) {
    #pragma unroll
    for (int o = 16; o; o >>= 1) v += __shfl_xor_sync(0xffffffffu, v, o);
    return v;
}
__device__ __forceinline__ int ld_acq(volatile int* p) {
    int v;
    asm volatile("ld.acquire.gpu.s32 %0, [%1];" : "=r"(v) : "l"((int*)p) : "memory");
    return v;
}
__device__ __forceinline__ void st_rel(volatile int* p, int v) {
    asm volatile("st.release.gpu.s32 [%0], %1;" :: "l"((int*)p), "r"(v) : "memory");
}
__device__ __forceinline__ int imin(int a, int b) { return a < b ? a : b; }
__device__ __forceinline__ int imax(int a, int b) { return a > b ? a : b; }

extern __shared__ float s_dyn[];   // [PCACHE*1024] enc rows | [31*512] w_out summary half

__global__ void __launch_bounds__(NTHR, 1)
decoder_kernel(const float* __restrict__ enc,     // [TENC, 1024] keys|values
               const float* __restrict__ embed,   // [31, 512]
               const float* __restrict__ w_ih,    // [1536, 512]
               const float* __restrict__ w_hh,    // [1536, 512]
               const float* __restrict__ b_ih,    // [1536]
               const float* __restrict__ b_hh,    // [1536]
               const float* __restrict__ w_out,   // [31, 1024]
               const float* __restrict__ b_out,   // [31]
               float* __restrict__ out)
{
    const int tid  = threadIdx.x;
    const int blk  = blockIdx.x;
    const int nblk = gridDim.x;
    const int wid  = tid >> 5;
    const int lane = tid & 31;
    const int base = lane * 4;

    float* s_enc   = s_dyn;                   // PCACHE rows of enc
    float* s_woutS = s_dyn + PCACHE * 1024;   // [31][512] summary-half of w_out

    __shared__ __align__(16) float s_hh[HID];          // h (per-block copy)
    __shared__ __align__(16) float s_sum[HID];         // block partial summary
    __shared__ __align__(16) float s_warp[8][HID];     // merge buffers
    __shared__ float s_exp[128];
    __shared__ unsigned s_mask[4];                     // per-row PAD masks (constant)
    __shared__ float s_red[NW];
    __shared__ int   s_best;

    float* out_logits = out;                        // [100, 31]
    float* out_len    = out + MAXLEN * NVOCAB;      // [1]
    float* out_attn   = out + MAXLEN * NVOCAB + 1;  // [100, 16384]

    int ep = g_release;   // persistent epoch base

    // two-hop barrier: padded arrive flags -> block0 gather -> single release word
    auto grid_barrier = [&]() {
        ep++;
        __syncthreads();
        if (blk == 0) {
            if (tid == 0) st_rel(&g_arrive[0], ep);
            for (int i = tid; i < nblk; i += NTHR)
                if (i > 0) { while (ld_acq(&g_arrive[i * LDSTRIDE]) < ep) { } }
            __syncthreads();
            if (tid == 0) st_rel(&g_release, ep);
        } else {
            if (tid == 0) {
                st_rel(&g_arrive[blk * LDSTRIDE], ep);
                while (ld_acq(&g_release) < ep) { }
            }
        }
        __syncthreads();
    };

    // ---------------- per-launch init ----------------
    s_hh[tid] = 0.0f;                     // h0 = 0   (NTHR == HID)
    if (tid == 0) s_best = EOSI;          // y0 = embed[EOS]
    if (tid < 4) s_mask[tid] = 0u;

    // row partition: gh-duty blocks (32..127) get w rows; others w+7(+1)
    const int nd  = nblk - 96;
    const int w   = (TENC - 7 * nd) / nblk;
    const int rem = TENC - 96 * w - nd * (w + 7);
    int t0, rows;
    if (blk < 32) {
        t0 = blk * (w + 7) + imin(blk, rem);
        rows = w + 7 + (blk < rem ? 1 : 0);
    } else if (blk < 128) {
        t0 = 32 * (w + 7) + imin(32, rem) + (blk - 32) * w;
        rows = w;
    } else {
        const int idx = blk - 128 + 32;
        t0 = 32 * (w + 7) + imin(32, rem) + 96 * w
           + (blk - 128) * (w + 7) + imax(0, imin(idx, rem) - 32);
        rows = w + 7 + (idx < rem ? 1 : 0);
    }
    const int t1 = t0 + rows;
    const int ts = t0 + PCACHE;           // stream start (rows > PCACHE always)

    // pin first PCACHE rows of our range into smem (once per launch)
    for (int i = tid; i < PCACHE * 1024; i += NTHR)
        s_enc[i] = __ldcg(enc + (size_t)t0 * 1024 + i);
    // w_out summary half -> smem
    for (int i = tid; i < NVOCAB * HID; i += NTHR)
        s_woutS[i] = w_out[(size_t)(i >> 9) * 1024 + (i & 511)];

    if (blk == 0) {
        g_gh[0][0][tid] = b_hh[tid];
        g_gh[0][1][tid] = b_hh[tid + HID];
        g_gh[0][2][tid] = b_hh[tid + 2 * HID];
        if (wid == 1 && lane < NVOCAB) {
            #pragma unroll
            for (int b = 0; b < NBUF; ++b) g_ldot[b][lane * LDSTRIDE] = 0.0f;
        }
        if (tid == 0) { g_tot[0] = 0.0f; g_tot[1] = 0.0f; g_tot[2] = 0.0f; }
    }
    // gx table: gx[v][u] = w_ih[u] . embed[v] + b_ih[u]
    {
        const int gw = blk * NW + wid;
        for (int r = gw; r < NVOCAB * 3 * HID; r += nblk * NW) {
            const int v = r / (3 * HID);
            const int u = r - v * (3 * HID);
            const float* wrow = w_ih + (size_t)u * HID;
            const float* erow = embed + (size_t)v * HID;
            float a = 0.0f;
            #pragma unroll
            for (int m = 0; m < 4; ++m) {
                int c = base + m * 128;
                float4 w4 = *(const float4*)(wrow + c);
                float4 e4 = *(const float4*)(erow + c);
                a = fmaf(w4.x, e4.x, fmaf(w4.y, e4.y, fmaf(w4.z, e4.z, fmaf(w4.w, e4.w, a))));
            }
            a = warp_allsum(a);
            if (lane == 0) g_gx[v][u] = a + b_ih[u];
        }
    }
    __syncthreads();
    // ---- precompute PAD masks (keys constant across steps) ----
    for (int t = t0 + wid; t < t1; t += NW) {
        const float* row = enc + (size_t)t * (2 * HID);
        float4 k0 = __ldcg((const float4*)(row + base));
        float4 k1 = __ldcg((const float4*)(row + base + 128));
        float4 k2 = __ldcg((const float4*)(row + base + 256));
        float4 k3 = __ldcg((const float4*)(row + base + 384));
        int ok = (k0.x != PADV) | (k0.y != PADV) | (k0.z != PADV) | (k0.w != PADV)
               | (k1.x != PADV) | (k1.y != PADV) | (k1.z != PADV) | (k1.w != PADV)
               | (k2.x != PADV) | (k2.y != PADV) | (k2.z != PADV) | (k2.w != PADV)
               | (k3.x != PADV) | (k3.y != PADV) | (k3.z != PADV) | (k3.w != PADV);
        ok = __any_sync(0xffffffffu, ok);
        if (lane == 0 && ok) atomicOr(&s_mask[(t - t0) >> 5], 1u << ((t - t0) & 31));
    }
    int eos_step = MAXLEN;

    grid_barrier();

    const float scale = 0.04419417382415922f;   // 1/sqrt(512)

    for (int k = 0; k <= MAXLEN; ++k) {
        // ============ Phase A: tiny epilogue of step k-1 (redundant per block) ============
        if (k > 0) {
            const int p  = (k - 1) % NBUF;
            const int pl = (k - 1) & 1;
            const float inv_total = 1.0f / g_tot[p];

            // prefetch gh for the GRU (independent of argmax)
            const int pg = k & 1;
            const float gh0 = g_gh[pg][0][tid];
            const float gh1 = g_gh[pg][1][tid];
            const float gh2 = g_gh[pg][2][tid];

            if (wid == 0) {
                float lg = -1e30f;
                if (lane < NVOCAB)
                    lg = g_ldot[p][lane * LDSTRIDE] * inv_total + g_lh[pl][lane];
                // shfl argmax, first-index tie-break
                unsigned kb = __float_as_uint(lg);
                kb = (kb & 0x80000000u) ? ~kb : (kb | 0x80000000u);
                unsigned long long pk = ((unsigned long long)kb << 6) | (unsigned)(63 - lane);
                #pragma unroll
                for (int o = 16; o; o >>= 1) {
                    unsigned long long q = __shfl_xor_sync(0xffffffffu, pk, o);
                    if (q > pk) pk = q;
                }
                if (lane == 0) {
                    int best = 63 - (int)(pk & 63u);
                    s_best = best;
                    if (blk == 0 && best == EOSI && eos_step == MAXLEN) eos_step = k - 1;
                }
                if (blk == 0 && lane < NVOCAB)
                    out_logits[(k - 1) * NVOCAB + lane] = lg;
            }
            // zero buffer (k+1)%3 (block 0, warp 1)
            if (blk == 0 && wid == 1) {
                const int zb = (k + 1) % NBUF;
                if (lane < NVOCAB) g_ldot[zb][lane * LDSTRIDE] = 0.0f;
                if (lane == 31) g_tot[zb] = 0.0f;
            }
            // attention output for step k-1
            for (int t = t0 + tid; t < t1; t += NTHR)
                out_attn[(size_t)(k - 1) * TENC + t] = s_exp[t - t0] * inv_total;
            __syncthreads();

            if (k == MAXLEN) break;

            // GRU pointwise: h^{(k)} = GRU(gx[best], gh, h^{(k-1)})
            const float* gx = g_gx[s_best];
            float r = 1.0f / (1.0f + __expf(-(gx[tid]           + gh0)));
            float z = 1.0f / (1.0f + __expf(-(gx[tid + HID]     + gh1)));
            float n = tanhf(gx[tid + 2 * HID] + r * gh2);
            s_hh[tid] = (1.0f - z) * n + z * s_hh[tid];
            __syncthreads();
        } else {
            // k == 0: h^{(0)} = GRU(gx[EOS], b_hh, 0)
            const float* gx = g_gx[EOSI];
            float r = 1.0f / (1.0f + __expf(-(gx[tid]           + g_gh[0][0][tid])));
            float z = 1.0f / (1.0f + __expf(-(gx[tid + HID]     + g_gh[0][1][tid])));
            float n = tanhf(gx[tid + 2 * HID] + r * g_gh[0][2][tid]);
            s_hh[tid] = (1.0f - z) * n;
            __syncthreads();
        }

        // ============ Phase B: attention sweep ============
        float4 h0 = *(const float4*)(s_hh + base);
        float4 h1 = *(const float4*)(s_hh + base + 128);
        float4 h2 = *(const float4*)(s_hh + base + 256);
        float4 h3 = *(const float4*)(s_hh + base + 384);

        // lh duty: blocks 1..31, warp 0: g_lh[k&1][v] = w_out[v,512:].h + b_out[v]
        if (wid == 0 && blk >= 1 && blk <= NVOCAB) {
            const int v = blk - 1;
            const float* wrow = w_out + (size_t)v * 1024 + HID;
            float dot = 0.0f;
            float4 w4;
            w4 = *(const float4*)(wrow + base);
            dot = fmaf(w4.x, h0.x, fmaf(w4.y, h0.y, fmaf(w4.z, h0.z, fmaf(w4.w, h0.w, dot))));
            w4 = *(const float4*)(wrow + base + 128);
            dot = fmaf(w4.x, h1.x, fmaf(w4.y, h1.y, fmaf(w4.z, h1.z, fmaf(w4.w, h1.w, dot))));
            w4 = *(const float4*)(wrow + base + 256);
            dot = fmaf(w4.x, h2.x, fmaf(w4.y, h2.y, fmaf(w4.z, h2.z, fmaf(w4.w, h2.w, dot))));
            w4 = *(const float4*)(wrow + base + 384);
            dot = fmaf(w4.x, h3.x, fmaf(w4.y, h3.y, fmaf(w4.z, h3.z, fmaf(w4.w, h3.w, dot))));
            dot = warp_allsum(dot);
            if (lane == 0) g_lh[k & 1][v] = dot + b_out[v];
        }

        float4 acc0 = {0,0,0,0}, acc1 = {0,0,0,0}, acc2 = {0,0,0,0}, acc3 = {0,0,0,0};
        float esum = 0.0f;

        // ---- streamed rows: software-pipelined, 1 row/iter, fused K+V ----
        {
            // prologue: load first row
            float4 k0, k1, k2, k3, v0, v1, v2, v3;
            int t = ts + wid;
            if (t < t1) {
                const float* row = enc + (size_t)t * (2 * HID);
                k0 = __ldcg((const float4*)(row + base));
                k1 = __ldcg((const float4*)(row + base + 128));
                k2 = __ldcg((const float4*)(row + base + 256));
                k3 = __ldcg((const float4*)(row + base + 384));
                v0 = __ldcg((const float4*)(row + HID + base));
                v1 = __ldcg((const float4*)(row + HID + base + 128));
                v2 = __ldcg((const float4*)(row + HID + base + 256));
                v3 = __ldcg((const float4*)(row + HID + base + 384));
            }
            for (; t < t1; t += NW) {
                // issue NEXT row's loads before this row's reduce tail
                const int tn = t + NW;
                const int hn = tn < t1;
                float4 nk0, nk1, nk2, nk3, nv0, nv1, nv2, nv3;
                {
                    const float* rn = enc + (size_t)(hn ? tn : t) * (2 * HID);
                    nk0 = __ldcg((const float4*)(rn + base));
                    nk1 = __ldcg((const float4*)(rn + base + 128));
                    nk2 = __ldcg((const float4*)(rn + base + 256));
                    nk3 = __ldcg((const float4*)(rn + base + 384));
                    nv0 = __ldcg((const float4*)(rn + HID + base));
                    nv1 = __ldcg((const float4*)(rn + HID + base + 128));
                    nv2 = __ldcg((const float4*)(rn + HID + base + 256));
                    nv3 = __ldcg((const float4*)(rn + HID + base + 384));
                }
                // compute current row
                float p0 = k0.x*h0.x + k0.y*h0.y + k0.z*h0.z + k0.w*h0.w;
                float p1 = k1.x*h1.x + k1.y*h1.y + k1.z*h1.z + k1.w*h1.w;
                float p2 = k2.x*h2.x + k2.y*h2.y + k2.z*h2.z + k2.w*h2.w;
                float p3 = k3.x*h3.x + k3.y*h3.y + k3.z*h3.z + k3.w*h3.w;
                float d = (p0 + p1) + (p2 + p3);
                d = warp_allsum(d);
                const int it = t - t0;
                const unsigned m = (s_mask[it >> 5] >> (it & 31)) & 1u;
                float e = m ? __expf(d * scale) : 0.0f;
                if (lane == 0) { s_exp[it] = e; esum += e; }
                acc0.x = fmaf(e, v0.x, acc0.x); acc0.y = fmaf(e, v0.y, acc0.y);
                acc0.z = fmaf(e, v0.z, acc0.z); acc0.w = fmaf(e, v0.w, acc0.w);
                acc1.x = fmaf(e, v1.x, acc1.x); acc1.y = fmaf(e, v1.y, acc1.y);
                acc1.z = fmaf(e, v1.z, acc1.z); acc1.w = fmaf(e, v1.w, acc1.w);
                acc2.x = fmaf(e, v2.x, acc2.x); acc2.y = fmaf(e, v2.y, acc2.y);
                acc2.z = fmaf(e, v2.z, acc2.z); acc2.w = fmaf(e, v2.w, acc2.w);
                acc3.x = fmaf(e, v3.x, acc3.x); acc3.y = fmaf(e, v3.y, acc3.y);
                acc3.z = fmaf(e, v3.z, acc3.z); acc3.w = fmaf(e, v3.w, acc3.w);
                // rotate buffers
                k0 = nk0; k1 = nk1; k2 = nk2; k3 = nk3;
                v0 = nv0; v1 = nv1; v2 = nv2; v3 = nv3;
            }
        }

        // ---- pinned rows (smem) ----
        for (int t = t0 + wid; t < ts; t += NW) {
            const float* row = s_enc + (size_t)(t - t0) * (2 * HID);
            float4 k0 = *(const float4*)(row + base);
            float4 k1 = *(const float4*)(row + base + 128);
            float4 k2 = *(const float4*)(row + base + 256);
            float4 k3 = *(const float4*)(row + base + 384);
            float4 v0 = *(const float4*)(row + HID + base);
            float4 v1 = *(const float4*)(row + HID + base + 128);
            float4 v2 = *(const float4*)(row + HID + base + 256);
            float4 v3 = *(const float4*)(row + HID + base + 384);
            float p0 = k0.x*h0.x + k0.y*h0.y + k0.z*h0.z + k0.w*h0.w;
            float p1 = k1.x*h1.x + k1.y*h1.y + k1.z*h1.z + k1.w*h1.w;
            float p2 = k2.x*h2.x + k2.y*h2.y + k2.z*h2.z + k2.w*h2.w;
            float p3 = k3.x*h3.x + k3.y*h3.y + k3.z*h3.z + k3.w*h3.w;
            float d = (p0 + p1) + (p2 + p3);
            d = warp_allsum(d);
            const int it = t - t0;
            const unsigned m = (s_mask[it >> 5] >> (it & 31)) & 1u;
            float e = m ? __expf(d * scale) : 0.0f;
            if (lane == 0) { s_exp[it] = e; esum += e; }
            acc0.x = fmaf(e, v0.x, acc0.x); acc0.y = fmaf(e, v0.y, acc0.y);
            acc0.z = fmaf(e, v0.z, acc0.z); acc0.w = fmaf(e, v0.w, acc0.w);
            acc1.x = fmaf(e, v1.x, acc1.x); acc1.y = fmaf(e, v1.y, acc1.y);
            acc1.z = fmaf(e, v1.z, acc1.z); acc1.w = fmaf(e, v1.w, acc1.w);
            acc2.x = fmaf(e, v2.x, acc2.x); acc2.y = fmaf(e, v2.y, acc2.y);
            acc2.z = fmaf(e, v2.z, acc2.z); acc2.w = fmaf(e, v2.w, acc2.w);
            acc3.x = fmaf(e, v3.x, acc3.x); acc3.y = fmaf(e, v3.y, acc3.y);
            acc3.z = fmaf(e, v3.z, acc3.z); acc3.w = fmaf(e, v3.w, acc3.w);
        }

        // gh duty: blocks 32..127, one dot per warp (1536 total)
        if (blk >= 32 && blk < 128) {
            const int d  = (blk - 32) * NW + wid;   // 0..1535
            const int g  = d >> 9;
            const int j  = d & 511;
            const int pn = (k + 1) & 1;
            const float* ur = w_hh + (size_t)(g * HID + j) * HID;
            float a = 0.0f;
            #pragma unroll
            for (int m = 0; m < 4; ++m) {
                int c = base + m * 128;
                float4 hx = *(const float4*)(s_hh + c);
                float4 u4 = *(const float4*)(ur + c);
                a = fmaf(hx.x, u4.x, fmaf(hx.y, u4.y, fmaf(hx.z, u4.z, fmaf(hx.w, u4.w, a))));
            }
            a = warp_allsum(a);
            if (lane == 0) g_gh[pn][g][j] = a + b_hh[g * HID + j];
        }

        // ---- merge: two-phase staging (8 buffers), no smem atomics ----
        if (lane == 0) s_red[wid] = esum;
        if (wid < 8) {
            *(float4*)&s_warp[wid][base]       = acc0;
            *(float4*)&s_warp[wid][base + 128] = acc1;
            *(float4*)&s_warp[wid][base + 256] = acc2;
            *(float4*)&s_warp[wid][base + 384] = acc3;
        }
        __syncthreads();
        if (wid >= 8) {
            float* bdst = s_warp[wid - 8];
            float4 t;
            t = *(float4*)&bdst[base];
            t.x += acc0.x; t.y += acc0.y; t.z += acc0.z; t.w += acc0.w;
            *(float4*)&bdst[base] = t;
            t = *(float4*)&bdst[base + 128];
            t.x += acc1.x; t.y += acc1.y; t.z += acc1.z; t.w += acc1.w;
            *(float4*)&bdst[base + 128] = t;
            t = *(float4*)&bdst[base + 256];
            t.x += acc2.x; t.y += acc2.y; t.z += acc2.z; t.w += acc2.w;
            *(float4*)&bdst[base + 256] = t;
            t = *(float4*)&bdst[base + 384];
            t.x += acc3.x; t.y += acc3.y; t.z += acc3.z; t.w += acc3.w;
            *(float4*)&bdst[base + 384] = t;
        }
        __syncthreads();
        {
            float colsum = 0.0f;
            #pragma unroll
            for (int w8 = 0; w8 < 8; ++w8) colsum += s_warp[w8][tid];
            s_sum[tid] = colsum;
        }
        __syncthreads();

        // ---- partial logit dots: ldot[v] += w_outS[v] . s_sum  (31 atomics/block) ----
        const int bb = k % NBUF;
        for (int v = wid; v < NVOCAB; v += NW) {
            const float* wrow = s_woutS + v * HID;
            float dot = 0.0f;
            #pragma unroll
            for (int m = 0; m < 4; ++m) {
                int c = base + m * 128;
                float4 w4 = *(const float4*)(wrow + c);
                float4 x4 = *(const float4*)(s_sum + c);
                dot = fmaf(w4.x, x4.x, fmaf(w4.y, x4.y, fmaf(w4.z, x4.z, fmaf(w4.w, x4.w, dot))));
            }
            dot = warp_allsum(dot);
            if (lane == 0) atomicAdd(&g_ldot[bb][v * LDSTRIDE], dot);
        }
        if (tid == 0) {
            float tot = 0.0f;
            #pragma unroll
            for (int w8 = 0; w8 < NW; ++w8) tot += s_red[w8];
            atomicAdd(&g_tot[bb], tot);
        }

        grid_barrier();   // the one barrier per step
    }

    if (blk == 0 && tid == 0) out_len[0] = (float)eos_step;
}

extern "C" void kernel_launch(void* const* d_in, const int* in_sizes, int n_in,
                              void* d_out, int out_size) {
    const float* enc   = (const float*)d_in[0];   // encoding [1,16384,1024]
    const float* embed = (const float*)d_in[2];
    const float* w_ih  = (const float*)d_in[3];
    const float* w_hh  = (const float*)d_in[4];
    const float* b_ih  = (const float*)d_in[5];
    const float* b_hh  = (const float*)d_in[6];
    const float* w_out = (const float*)d_in[7];
    const float* b_out = (const float*)d_in[8];
    (void)in_sizes; (void)n_in; (void)out_size;

    const int smem_dyn = (PCACHE * 1024 + NVOCAB * HID) * sizeof(float);   // 202752 B
    static int nblk = 0;
    if (!nblk) {
        cudaFuncSetAttribute(decoder_kernel,
                             cudaFuncAttributeMaxDynamicSharedMemorySize, smem_dyn);
        int dev = 0;
        cudaGetDevice(&dev);
        int sms = 0;
        cudaDeviceGetAttribute(&sms, cudaDevAttrMultiProcessorCount, dev);
        nblk = (sms >= 128 && sms <= MAXBLK) ? sms : 148;
    }
    decoder_kernel<<<nblk, NTHR, smem_dyn>>>(enc, embed, w_ih, w_hh, b_ih, b_hh,
                                             w_out, b_out, (float*)d_out);
}

// round 14
// speedup vs baseline: 1.0933x; 1.0504x over previous
#include <cuda_runtime.h>
#include <math.h>

#define NTHR   512
#define NW     (NTHR / 32)        // 16 warps
#define HID    512
#define TENC   16384
#define NVOCAB 31
#define MAXLEN 100
#define EOSI   29
#define PADV   30.0f
#define NBUF   3
#define MAXBLK 256
#define PCACHE 34                 // enc rows pinned in smem per block
#define LDSTRIDE 32               // 128B padding stride

// ---------------- device scratch ----------------
__device__ float g_ldot[NBUF][NVOCAB * LDSTRIDE];     // partial logit dots (summary part)
__device__ float g_tot[NBUF];                         // softmax denominators
__device__ __align__(16) float g_gh[2][3][HID];       // w_hh@h + b_hh (r,z,n), double buffered
__device__ __align__(16) float g_gx[NVOCAB][3 * HID]; // w_ih@embed[v] + b_ih
__device__ float g_lh[2][NVOCAB];                     // w_out[:,512:]@h + b_out, double buffered
__device__ volatile int g_count_b;                    // barrier arrival counter
__device__ volatile int g_gen;                        // barrier generation word

__device__ __forceinline__ float warp_allsum(float v) {
    #pragma unroll
    for (int o = 16; o; o >>= 1) v += __shfl_xor_sync(0xffffffffu, v, o);
    return v;
}
__device__ __forceinline__ int ld_acq(volatile int* p) {
    int v;
    asm volatile("ld.acquire.gpu.s32 %0, [%1];" : "=r"(v) : "l"((int*)p) : "memory");
    return v;
}
__device__ __forceinline__ void st_rel(volatile int* p, int v) {
    asm volatile("st.release.gpu.s32 [%0], %1;" :: "l"((int*)p), "r"(v) : "memory");
}
__device__ __forceinline__ int atom_add_acqrel(volatile int* p, int v) {
    int old;
    asm volatile("atom.acq_rel.gpu.global.add.s32 %0, [%1], %2;"
                 : "=r"(old) : "l"((int*)p), "r"(v) : "memory");
    return old;
}
__device__ __forceinline__ int imin(int a, int b) { return a < b ? a : b; }

extern __shared__ float s_dyn[];   // [PCACHE*1024] enc rows | [31*512] w_out summary half

__global__ void __launch_bounds__(NTHR, 1)
decoder_kernel(const float* __restrict__ enc,     // [TENC, 1024] keys|values
               const float* __restrict__ embed,   // [31, 512]
               const float* __restrict__ w_ih,    // [1536, 512]
               const float* __restrict__ w_hh,    // [1536, 512]
               const float* __restrict__ b_ih,    // [1536]
               const float* __restrict__ b_hh,    // [1536]
               const float* __restrict__ w_out,   // [31, 1024]
               const float* __restrict__ b_out,   // [31]
               float* __restrict__ out)
{
    const int tid  = threadIdx.x;
    const int blk  = blockIdx.x;
    const int nblk = gridDim.x;
    const int wid  = tid >> 5;
    const int lane = tid & 31;
    const int base = lane * 4;

    float* s_enc   = s_dyn;                   // PCACHE rows of enc
    float* s_woutS = s_dyn + PCACHE * 1024;   // [31][512] summary-half of w_out

    __shared__ __align__(16) float s_hh[HID];          // h (per-block copy)
    __shared__ __align__(16) float s_sum[HID];         // block partial summary
    __shared__ __align__(16) float s_warp[8][HID];     // merge buffers
    __shared__ float s_exp[128];
    __shared__ unsigned s_mask[4];                     // per-row PAD masks (constant)
    __shared__ float s_red[NW];
    __shared__ int   s_best;

    float* out_logits = out;                        // [100, 31]
    float* out_len    = out + MAXLEN * NVOCAB;      // [1]
    float* out_attn   = out + MAXLEN * NVOCAB + 1;  // [100, 16384]

    int ep = g_gen;   // persistent epoch base (stable: gen only advances after ALL blocks arrive)

    // single-hop barrier: acq_rel counter; last arriver resets + publishes generation
    auto grid_barrier = [&]() {
        ep++;
        __syncthreads();
        if (tid == 0) {
            int old = atom_add_acqrel(&g_count_b, 1);
            if (old == nblk - 1) {
                g_count_b = 0;              // reset (ordered before release below)
                st_rel(&g_gen, ep);
            } else {
                while (ld_acq(&g_gen) < ep) { }
            }
        }
        __syncthreads();
    };

    // ---------------- per-launch init ----------------
    s_hh[tid] = 0.0f;                     // h0 = 0   (NTHR == HID)
    if (tid == 0) s_best = EOSI;          // y0 = embed[EOS]
    if (tid < 4) s_mask[tid] = 0u;

    // ---- near-uniform row partition; duty blocks 32..63 get the short rows ----
    const int nrows = TENC / nblk;
    const int extra = TENC - nrows * nblk;    // assumed >= 32 (holds for 148/152)
    int t0, rows;
    if (blk < 32)      { t0 = nrows * blk + blk;  rows = nrows + 1; }
    else if (blk < 64) { t0 = nrows * blk + 32;   rows = nrows;     }
    else {
        const int b3 = imin(blk - 64, extra - 32);
        t0 = nrows * blk + 32 + b3;
        rows = nrows + ((blk - 64) < (extra - 32) ? 1 : 0);
    }
    const int t1 = t0 + rows;
    const int ts = t0 + PCACHE;           // stream start (rows > PCACHE always)

    // pin first PCACHE rows of our range into smem (once per launch)
    for (int i = tid; i < PCACHE * 1024; i += NTHR)
        s_enc[i] = __ldcg(enc + (size_t)t0 * 1024 + i);
    // w_out summary half -> smem
    for (int i = tid; i < NVOCAB * HID; i += NTHR)
        s_woutS[i] = w_out[(size_t)(i >> 9) * 1024 + (i & 511)];

    if (blk == 0) {
        g_gh[0][0][tid] = b_hh[tid];
        g_gh[0][1][tid] = b_hh[tid + HID];
        g_gh[0][2][tid] = b_hh[tid + 2 * HID];
        if (wid == 1 && lane < NVOCAB) {
            #pragma unroll
            for (int b = 0; b < NBUF; ++b) g_ldot[b][lane * LDSTRIDE] = 0.0f;
        }
        if (tid == 0) { g_tot[0] = 0.0f; g_tot[1] = 0.0f; g_tot[2] = 0.0f; }
    }
    // gx table: gx[v][u] = w_ih[u] . embed[v] + b_ih[u]
    {
        const int gw = blk * NW + wid;
        for (int r = gw; r < NVOCAB * 3 * HID; r += nblk * NW) {
            const int v = r / (3 * HID);
            const int u = r - v * (3 * HID);
            const float* wrow = w_ih + (size_t)u * HID;
            const float* erow = embed + (size_t)v * HID;
            float a = 0.0f;
            #pragma unroll
            for (int m = 0; m < 4; ++m) {
                int c = base + m * 128;
                float4 w4 = *(const float4*)(wrow + c);
                float4 e4 = *(const float4*)(erow + c);
                a = fmaf(w4.x, e4.x, fmaf(w4.y, e4.y, fmaf(w4.z, e4.z, fmaf(w4.w, e4.w, a))));
            }
            a = warp_allsum(a);
            if (lane == 0) g_gx[v][u] = a + b_ih[u];
        }
    }
    __syncthreads();
    // ---- precompute PAD masks (keys constant across steps) ----
    for (int t = t0 + wid; t < t1; t += NW) {
        const float* row = enc + (size_t)t * (2 * HID);
        float4 k0 = __ldcg((const float4*)(row + base));
        float4 k1 = __ldcg((const float4*)(row + base + 128));
        float4 k2 = __ldcg((const float4*)(row + base + 256));
        float4 k3 = __ldcg((const float4*)(row + base + 384));
        int ok = (k0.x != PADV) | (k0.y != PADV) | (k0.z != PADV) | (k0.w != PADV)
               | (k1.x != PADV) | (k1.y != PADV) | (k1.z != PADV) | (k1.w != PADV)
               | (k2.x != PADV) | (k2.y != PADV) | (k2.z != PADV) | (k2.w != PADV)
               | (k3.x != PADV) | (k3.y != PADV) | (k3.z != PADV) | (k3.w != PADV);
        ok = __any_sync(0xffffffffu, ok);
        if (lane == 0 && ok) atomicOr(&s_mask[(t - t0) >> 5], 1u << ((t - t0) & 31));
    }
    int eos_step = MAXLEN;

    grid_barrier();

    const float scale = 0.04419417382415922f;   // 1/sqrt(512)

    for (int k = 0; k <= MAXLEN; ++k) {
        // ============ Phase A: epilogue of step k-1 (argmax || attn-write in parallel) ============
        if (k > 0) {
            const int p  = (k - 1) % NBUF;
            const int pl = (k - 1) & 1;
            const float inv_total = 1.0f / g_tot[p];

            // prefetch gh for the GRU (independent of argmax)
            const int pg = k & 1;
            const float gh0 = g_gh[pg][0][tid];
            const float gh1 = g_gh[pg][1][tid];
            const float gh2 = g_gh[pg][2][tid];

            if (wid == 0) {
                float lg = -1e30f;
                if (lane < NVOCAB)
                    lg = g_ldot[p][lane * LDSTRIDE] * inv_total + g_lh[pl][lane];
                // shfl argmax, first-index tie-break
                unsigned kb = __float_as_uint(lg);
                kb = (kb & 0x80000000u) ? ~kb : (kb | 0x80000000u);
                unsigned long long pk = ((unsigned long long)kb << 6) | (unsigned)(63 - lane);
                #pragma unroll
                for (int o = 16; o; o >>= 1) {
                    unsigned long long q = __shfl_xor_sync(0xffffffffu, pk, o);
                    if (q > pk) pk = q;
                }
                if (lane == 0) {
                    int best = 63 - (int)(pk & 63u);
                    s_best = best;
                    if (blk == 0 && best == EOSI && eos_step == MAXLEN) eos_step = k - 1;
                }
                if (blk == 0 && lane < NVOCAB)
                    out_logits[(k - 1) * NVOCAB + lane] = lg;
            } else if (wid == 1) {
                // zero buffer (k+1)%3 (block 0 only)
                if (blk == 0) {
                    const int zb = (k + 1) % NBUF;
                    if (lane < NVOCAB) g_ldot[zb][lane * LDSTRIDE] = 0.0f;
                    if (lane == 31) g_tot[zb] = 0.0f;
                }
            } else {
                // warps 2..15 write the attention output for step k-1 (hidden behind argmax)
                for (int t = t0 + (tid - 64); t < t1; t += NTHR - 64)
                    out_attn[(size_t)(k - 1) * TENC + t] = s_exp[t - t0] * inv_total;
            }
            __syncthreads();

            if (k == MAXLEN) break;

            // GRU pointwise: h^{(k)} = GRU(gx[best], gh, h^{(k-1)})
            const float* gx = g_gx[s_best];
            float r = 1.0f / (1.0f + __expf(-(gx[tid]           + gh0)));
            float z = 1.0f / (1.0f + __expf(-(gx[tid + HID]     + gh1)));
            float n = tanhf(gx[tid + 2 * HID] + r * gh2);
            s_hh[tid] = (1.0f - z) * n + z * s_hh[tid];
            __syncthreads();
        } else {
            // k == 0: h^{(0)} = GRU(gx[EOS], b_hh, 0)
            const float* gx = g_gx[EOSI];
            float r = 1.0f / (1.0f + __expf(-(gx[tid]           + g_gh[0][0][tid])));
            float z = 1.0f / (1.0f + __expf(-(gx[tid + HID]     + g_gh[0][1][tid])));
            float n = tanhf(gx[tid + 2 * HID] + r * g_gh[0][2][tid]);
            s_hh[tid] = (1.0f - z) * n;
            __syncthreads();
        }

        // ============ Phase B: attention sweep ============
        float4 h0 = *(const float4*)(s_hh + base);
        float4 h1 = *(const float4*)(s_hh + base + 128);
        float4 h2 = *(const float4*)(s_hh + base + 256);
        float4 h3 = *(const float4*)(s_hh + base + 384);

        // lh duty: blocks 32..62 (the short-row blocks), warp 0
        if (wid == 0 && blk >= 32 && blk < 32 + NVOCAB) {
            const int v = blk - 32;
            const float* wrow = w_out + (size_t)v * 1024 + HID;
            float dot = 0.0f;
            float4 w4;
            w4 = *(const float4*)(wrow + base);
            dot = fmaf(w4.x, h0.x, fmaf(w4.y, h0.y, fmaf(w4.z, h0.z, fmaf(w4.w, h0.w, dot))));
            w4 = *(const float4*)(wrow + base + 128);
            dot = fmaf(w4.x, h1.x, fmaf(w4.y, h1.y, fmaf(w4.z, h1.z, fmaf(w4.w, h1.w, dot))));
            w4 = *(const float4*)(wrow + base + 256);
            dot = fmaf(w4.x, h2.x, fmaf(w4.y, h2.y, fmaf(w4.z, h2.z, fmaf(w4.w, h2.w, dot))));
            w4 = *(const float4*)(wrow + base + 384);
            dot = fmaf(w4.x, h3.x, fmaf(w4.y, h3.y, fmaf(w4.z, h3.z, fmaf(w4.w, h3.w, dot))));
            dot = warp_allsum(dot);
            if (lane == 0) g_lh[k & 1][v] = dot + b_out[v];
        }

        float4 acc0 = {0,0,0,0}, acc1 = {0,0,0,0}, acc2 = {0,0,0,0}, acc3 = {0,0,0,0};
        float esum = 0.0f;

        // ---- streamed rows: software-pipelined, 1 row/iter, fused K+V ----
        {
            float4 k0, k1, k2, k3, v0, v1, v2, v3;
            int t = ts + wid;
            if (t < t1) {
                const float* row = enc + (size_t)t * (2 * HID);
                k0 = __ldcg((const float4*)(row + base));
                k1 = __ldcg((const float4*)(row + base + 128));
                k2 = __ldcg((const float4*)(row + base + 256));
                k3 = __ldcg((const float4*)(row + base + 384));
                v0 = __ldcg((const float4*)(row + HID + base));
                v1 = __ldcg((const float4*)(row + HID + base + 128));
                v2 = __ldcg((const float4*)(row + HID + base + 256));
                v3 = __ldcg((const float4*)(row + HID + base + 384));
            }
            for (; t < t1; t += NW) {
                const int tn = t + NW;
                const int hn = tn < t1;
                float4 nk0, nk1, nk2, nk3, nv0, nv1, nv2, nv3;
                {
                    const float* rn = enc + (size_t)(hn ? tn : t) * (2 * HID);
                    nk0 = __ldcg((const float4*)(rn + base));
                    nk1 = __ldcg((const float4*)(rn + base + 128));
                    nk2 = __ldcg((const float4*)(rn + base + 256));
                    nk3 = __ldcg((const float4*)(rn + base + 384));
                    nv0 = __ldcg((const float4*)(rn + HID + base));
                    nv1 = __ldcg((const float4*)(rn + HID + base + 128));
                    nv2 = __ldcg((const float4*)(rn + HID + base + 256));
                    nv3 = __ldcg((const float4*)(rn + HID + base + 384));
                }
                float p0 = k0.x*h0.x + k0.y*h0.y + k0.z*h0.z + k0.w*h0.w;
                float p1 = k1.x*h1.x + k1.y*h1.y + k1.z*h1.z + k1.w*h1.w;
                float p2 = k2.x*h2.x + k2.y*h2.y + k2.z*h2.z + k2.w*h2.w;
                float p3 = k3.x*h3.x + k3.y*h3.y + k3.z*h3.z + k3.w*h3.w;
                float d = (p0 + p1) + (p2 + p3);
                d = warp_allsum(d);
                const int it = t - t0;
                const unsigned m = (s_mask[it >> 5] >> (it & 31)) & 1u;
                float e = m ? __expf(d * scale) : 0.0f;
                if (lane == 0) { s_exp[it] = e; esum += e; }
                acc0.x = fmaf(e, v0.x, acc0.x); acc0.y = fmaf(e, v0.y, acc0.y);
                acc0.z = fmaf(e, v0.z, acc0.z); acc0.w = fmaf(e, v0.w, acc0.w);
                acc1.x = fmaf(e, v1.x, acc1.x); acc1.y = fmaf(e, v1.y, acc1.y);
                acc1.z = fmaf(e, v1.z, acc1.z); acc1.w = fmaf(e, v1.w, acc1.w);
                acc2.x = fmaf(e, v2.x, acc2.x); acc2.y = fmaf(e, v2.y, acc2.y);
                acc2.z = fmaf(e, v2.z, acc2.z); acc2.w = fmaf(e, v2.w, acc2.w);
                acc3.x = fmaf(e, v3.x, acc3.x); acc3.y = fmaf(e, v3.y, acc3.y);
                acc3.z = fmaf(e, v3.z, acc3.z); acc3.w = fmaf(e, v3.w, acc3.w);
                k0 = nk0; k1 = nk1; k2 = nk2; k3 = nk3;
                v0 = nv0; v1 = nv1; v2 = nv2; v3 = nv3;
            }
        }

        // ---- pinned rows (smem) ----
        for (int t = t0 + wid; t < ts; t += NW) {
            const float* row = s_enc + (size_t)(t - t0) * (2 * HID);
            float4 k0 = *(const float4*)(row + base);
            float4 k1 = *(const float4*)(row + base + 128);
            float4 k2 = *(const float4*)(row + base + 256);
            float4 k3 = *(const float4*)(row + base + 384);
            float4 v0 = *(const float4*)(row + HID + base);
            float4 v1 = *(const float4*)(row + HID + base + 128);
            float4 v2 = *(const float4*)(row + HID + base + 256);
            float4 v3 = *(const float4*)(row + HID + base + 384);
            float p0 = k0.x*h0.x + k0.y*h0.y + k0.z*h0.z + k0.w*h0.w;
            float p1 = k1.x*h1.x + k1.y*h1.y + k1.z*h1.z + k1.w*h1.w;
            float p2 = k2.x*h2.x + k2.y*h2.y + k2.z*h2.z + k2.w*h2.w;
            float p3 = k3.x*h3.x + k3.y*h3.y + k3.z*h3.z + k3.w*h3.w;
            float d = (p0 + p1) + (p2 + p3);
            d = warp_allsum(d);
            const int it = t - t0;
            const unsigned m = (s_mask[it >> 5] >> (it & 31)) & 1u;
            float e = m ? __expf(d * scale) : 0.0f;
            if (lane == 0) { s_exp[it] = e; esum += e; }
            acc0.x = fmaf(e, v0.x, acc0.x); acc0.y = fmaf(e, v0.y, acc0.y);
            acc0.z = fmaf(e, v0.z, acc0.z); acc0.w = fmaf(e, v0.w, acc0.w);
            acc1.x = fmaf(e, v1.x, acc1.x); acc1.y = fmaf(e, v1.y, acc1.y);
            acc1.z = fmaf(e, v1.z, acc1.z); acc1.w = fmaf(e, v1.w, acc1.w);
            acc2.x = fmaf(e, v2.x, acc2.x); acc2.y = fmaf(e, v2.y, acc2.y);
            acc2.z = fmaf(e, v2.z, acc2.z); acc2.w = fmaf(e, v2.w, acc2.w);
            acc3.x = fmaf(e, v3.x, acc3.x); acc3.y = fmaf(e, v3.y, acc3.y);
            acc3.z = fmaf(e, v3.z, acc3.z); acc3.w = fmaf(e, v3.w, acc3.w);
        }

        // gh duty: blocks 32..127, one dot per warp (1536 total)
        if (blk >= 32 && blk < 128) {
            const int d  = (blk - 32) * NW + wid;   // 0..1535
            const int g  = d >> 9;
            const int j  = d & 511;
            const int pn = (k + 1) & 1;
            const float* ur = w_hh + (size_t)(g * HID + j) * HID;
            float a = 0.0f;
            #pragma unroll
            for (int m = 0; m < 4; ++m) {
                int c = base + m * 128;
                float4 hx = *(const float4*)(s_hh + c);
                float4 u4 = *(const float4*)(ur + c);
                a = fmaf(hx.x, u4.x, fmaf(hx.y, u4.y, fmaf(hx.z, u4.z, fmaf(hx.w, u4.w, a))));
            }
            a = warp_allsum(a);
            if (lane == 0) g_gh[pn][g][j] = a + b_hh[g * HID + j];
        }

        // ---- merge: two-phase staging (8 buffers), no smem atomics ----
        if (lane == 0) s_red[wid] = esum;
        if (wid < 8) {
            *(float4*)&s_warp[wid][base]       = acc0;
            *(float4*)&s_warp[wid][base + 128] = acc1;
            *(float4*)&s_warp[wid][base + 256] = acc2;
            *(float4*)&s_warp[wid][base + 384] = acc3;
        }
        __syncthreads();
        if (wid >= 8) {
            float* bdst = s_warp[wid - 8];
            float4 t;
            t = *(float4*)&bdst[base];
            t.x += acc0.x; t.y += acc0.y; t.z += acc0.z; t.w += acc0.w;
            *(float4*)&bdst[base] = t;
            t = *(float4*)&bdst[base + 128];
            t.x += acc1.x; t.y += acc1.y; t.z += acc1.z; t.w += acc1.w;
            *(float4*)&bdst[base + 128] = t;
            t = *(float4*)&bdst[base + 256];
            t.x += acc2.x; t.y += acc2.y; t.z += acc2.z; t.w += acc2.w;
            *(float4*)&bdst[base + 256] = t;
            t = *(float4*)&bdst[base + 384];
            t.x += acc3.x; t.y += acc3.y; t.z += acc3.z; t.w += acc3.w;
            *(float4*)&bdst[base + 384] = t;
        }
        __syncthreads();
        {
            float colsum = 0.0f;
            #pragma unroll
            for (int w8 = 0; w8 < 8; ++w8) colsum += s_warp[w8][tid];
            s_sum[tid] = colsum;
        }
        __syncthreads();

        // ---- partial logit dots: ldot[v] += w_outS[v] . s_sum  (31 atomics/block) ----
        const int bb = k % NBUF;
        for (int v = wid; v < NVOCAB; v += NW) {
            const float* wrow = s_woutS + v * HID;
            float dot = 0.0f;
            #pragma unroll
            for (int m = 0; m < 4; ++m) {
                int c = base + m * 128;
                float4 w4 = *(const float4*)(wrow + c);
                float4 x4 = *(const float4*)(s_sum + c);
                dot = fmaf(w4.x, x4.x, fmaf(w4.y, x4.y, fmaf(w4.z, x4.z, fmaf(w4.w, x4.w, dot))));
            }
            dot = warp_allsum(dot);
            if (lane == 0) atomicAdd(&g_ldot[bb][v * LDSTRIDE], dot);
        }
        if (tid == 0) {
            float tot = 0.0f;
            #pragma unroll
            for (int w8 = 0; w8 < NW; ++w8) tot += s_red[w8];
            atomicAdd(&g_tot[bb], tot);
        }

        grid_barrier();   // the one barrier per step
    }

    if (blk == 0 && tid == 0) out_len[0] = (float)eos_step;
}

extern "C" void kernel_launch(void* const* d_in, const int* in_sizes, int n_in,
                              void* d_out, int out_size) {
    const float* enc   = (const float*)d_in[0];   // encoding [1,16384,1024]
    const float* embed = (const float*)d_in[2];
    const float* w_ih  = (const float*)d_in[3];
    const float* w_hh  = (const float*)d_in[4];
    const float* b_ih  = (const float*)d_in[5];
    const float* b_hh  = (const float*)d_in[6];
    const float* w_out = (const float*)d_in[7];
    const float* b_out = (const float*)d_in[8];
    (void)in_sizes; (void)n_in; (void)out_size;

    const int smem_dyn = (PCACHE * 1024 + NVOCAB * HID) * sizeof(float);   // 202752 B
    static int nblk = 0;
    if (!nblk) {
        cudaFuncSetAttribute(decoder_kernel,
                             cudaFuncAttributeMaxDynamicSharedMemorySize, smem_dyn);
        int dev = 0;
        cudaGetDevice(&dev);
        int sms = 0;
        cudaDeviceGetAttribute(&sms, cudaDevAttrMultiProcessorCount, dev);
        nblk = (sms >= 128 && sms <= MAXBLK) ? sms : 148;
    }
    decoder_kernel<<<nblk, NTHR, smem_dyn>>>(enc, embed, w_ih, w_hh, b_ih, b_hh,
                                             w_out, b_out, (float*)d_out);
}

// round 16
// speedup vs baseline: 1.2229x; 1.1185x over previous
#include <cuda_runtime.h>
#include <cuda_fp16.h>
#include <math.h>

#define NTHR   512
#define NW     (NTHR / 32)        // 16 warps
#define HID    512
#define TENC   16384
#define NVOCAB 31
#define MAXLEN 100
#define EOSI   29
#define PADV   30.0f
#define NBUF   3
#define MAXBLK 256
#define PCACHE 48                 // fp16 enc rows pinned in smem per block
#define LDSTRIDE 32               // 128B padding stride

// ---------------- device scratch ----------------
__device__ __align__(16) __half2 g_enc16[(size_t)TENC * 512]; // fp16 copy of enc (33.5MB)
__device__ float g_ldot[NBUF][NVOCAB * LDSTRIDE];     // partial logit dots (summary part)
__device__ float g_tot[NBUF];                         // softmax denominators
__device__ __align__(16) float g_gh[2][3][HID];       // w_hh@h + b_hh (r,z,n), double buffered
__device__ __align__(16) float g_gx[NVOCAB][3 * HID]; // w_ih@embed[v] + b_ih
__device__ float g_lh[2][NVOCAB];                     // w_out[:,512:]@h + b_out, double buffered
__device__ volatile int g_count_b;                    // barrier arrival counter
__device__ volatile int g_gen;                        // barrier generation word

__device__ __forceinline__ float warp_allsum(float v) {
    #pragma unroll
    for (int o = 16; o; o >>= 1) v += __shfl_xor_sync(0xffffffffu, v, o);
    return v;
}
__device__ __forceinline__ int ld_acq(volatile int* p) {
    int v;
    asm volatile("ld.acquire.gpu.s32 %0, [%1];" : "=r"(v) : "l"((int*)p) : "memory");
    return v;
}
__device__ __forceinline__ void st_rel(volatile int* p, int v) {
    asm volatile("st.release.gpu.s32 [%0], %1;" :: "l"((int*)p), "r"(v) : "memory");
}
__device__ __forceinline__ int atom_add_acqrel(volatile int* p, int v) {
    int old;
    asm volatile("atom.acq_rel.gpu.global.add.s32 %0, [%1], %2;"
                 : "=r"(old) : "l"((int*)p), "r"(v) : "memory");
    return old;
}
__device__ __forceinline__ int imin(int a, int b) { return a < b ? a : b; }

// fused half2 pair -> two fp32 fma into d
#define H2FMA(d, u32, hx, hy) do {                                  \
    float2 _f = __half22float2(*(const __half2*)&(u32));            \
    d = fmaf(_f.x, (hx), fmaf(_f.y, (hy), d));                      \
} while (0)

// value half2 -> acc pair
#define H2ACC(accx, accy, u32, e) do {                              \
    float2 _f = __half22float2(*(const __half2*)&(u32));            \
    accx = fmaf((e), _f.x, accx); accy = fmaf((e), _f.y, accy);     \
} while (0)

extern __shared__ float s_dyn[];   // [PCACHE*512 floats] fp16 rows | [31*512] w_out summary half

__global__ void __launch_bounds__(NTHR, 1)
decoder_kernel(const float* __restrict__ enc,     // [TENC, 1024] keys|values
               const float* __restrict__ embed,   // [31, 512]
               const float* __restrict__ w_ih,    // [1536, 512]
               const float* __restrict__ w_hh,    // [1536, 512]
               const float* __restrict__ b_ih,    // [1536]
               const float* __restrict__ b_hh,    // [1536]
               const float* __restrict__ w_out,   // [31, 1024]
               const float* __restrict__ b_out,   // [31]
               float* __restrict__ out)
{
    const int tid  = threadIdx.x;
    const int blk  = blockIdx.x;
    const int nblk = gridDim.x;
    const int wid  = tid >> 5;
    const int lane = tid & 31;
    const int base = lane * 4;
    const int l8   = lane * 8;

    __half2* s_enc16 = (__half2*)s_dyn;            // PCACHE rows, 512 half2 each
    float*   s_woutS = s_dyn + PCACHE * 512;       // [31][512] summary-half of w_out

    __shared__ __align__(16) float s_hh[HID];
    __shared__ __align__(16) float s_sum[HID];
    __shared__ __align__(16) float s_warp[8][HID];
    __shared__ float s_exp[128];
    __shared__ unsigned s_mask[4];
    __shared__ float s_red[NW];
    __shared__ int   s_best;

    float* out_logits = out;
    float* out_len    = out + MAXLEN * NVOCAB;
    float* out_attn   = out + MAXLEN * NVOCAB + 1;

    int ep = g_gen;

    auto grid_barrier = [&]() {
        ep++;
        __syncthreads();
        if (tid == 0) {
            int old = atom_add_acqrel(&g_count_b, 1);
            if (old == nblk - 1) {
                g_count_b = 0;
                st_rel(&g_gen, ep);
            } else {
                while (ld_acq(&g_gen) < ep) { }
            }
        }
        __syncthreads();
    };

    // ---------------- per-launch init ----------------
    s_hh[tid] = 0.0f;
    if (tid == 0) s_best = EOSI;
    if (tid < 4) s_mask[tid] = 0u;

    // near-uniform row partition; duty blocks 32..63 get the short rows
    const int nrows = TENC / nblk;
    const int extra = TENC - nrows * nblk;
    int t0, rows;
    if (blk < 32)      { t0 = nrows * blk + blk;  rows = nrows + 1; }
    else if (blk < 64) { t0 = nrows * blk + 32;   rows = nrows;     }
    else {
        const int b3 = imin(blk - 64, extra - 32);
        t0 = nrows * blk + 32 + b3;
        rows = nrows + ((blk - 64) < (extra - 32) ? 1 : 0);
    }
    const int t1 = t0 + rows;
    const int ts = t0 + PCACHE;

    // ---- convert OWN rows to fp16 (block-local; no cross-block dependency) ----
    {
        const float2* src = (const float2*)(enc + (size_t)t0 * 1024);
        __half2*      dst = g_enc16 + (size_t)t0 * 512;
        const int     n   = rows * 512;
        for (int i = tid; i < n; i += NTHR) {
            float2 f = __ldcg(src + i);
            dst[i] = __floats2half2_rn(f.x, f.y);
        }
    }
    __syncthreads();
    // pin first PCACHE rows (fp16) into smem
    {
        const uint4* src = (const uint4*)(g_enc16 + (size_t)t0 * 512);
        uint4*       dst = (uint4*)s_enc16;
        for (int i = tid; i < PCACHE * 128; i += NTHR) dst[i] = src[i];
    }
    // w_out summary half -> smem
    for (int i = tid; i < NVOCAB * HID; i += NTHR)
        s_woutS[i] = w_out[(size_t)(i >> 9) * 1024 + (i & 511)];

    if (blk == 0) {
        g_gh[0][0][tid] = b_hh[tid];
        g_gh[0][1][tid] = b_hh[tid + HID];
        g_gh[0][2][tid] = b_hh[tid + 2 * HID];
        if (wid == 1 && lane < NVOCAB) {
            #pragma unroll
            for (int b = 0; b < NBUF; ++b) g_ldot[b][lane * LDSTRIDE] = 0.0f;
        }
        if (tid == 0) { g_tot[0] = 0.0f; g_tot[1] = 0.0f; g_tot[2] = 0.0f; }
    }
    // gx table
    {
        const int gw = blk * NW + wid;
        for (int r = gw; r < NVOCAB * 3 * HID; r += nblk * NW) {
            const int v = r / (3 * HID);
            const int u = r - v * (3 * HID);
            const float* wrow = w_ih + (size_t)u * HID;
            const float* erow = embed + (size_t)v * HID;
            float a = 0.0f;
            #pragma unroll
            for (int m = 0; m < 4; ++m) {
                int c = base + m * 128;
                float4 w4 = *(const float4*)(wrow + c);
                float4 e4 = *(const float4*)(erow + c);
                a = fmaf(w4.x, e4.x, fmaf(w4.y, e4.y, fmaf(w4.z, e4.z, fmaf(w4.w, e4.w, a))));
            }
            a = warp_allsum(a);
            if (lane == 0) g_gx[v][u] = a + b_ih[u];
        }
    }
    __syncthreads();
    // PAD masks from fp32 keys
    for (int t = t0 + wid; t < t1; t += NW) {
        const float* row = enc + (size_t)t * (2 * HID);
        float4 k0 = __ldcg((const float4*)(row + base));
        float4 k1 = __ldcg((const float4*)(row + base + 128));
        float4 k2 = __ldcg((const float4*)(row + base + 256));
        float4 k3 = __ldcg((const float4*)(row + base + 384));
        int ok = (k0.x != PADV) | (k0.y != PADV) | (k0.z != PADV) | (k0.w != PADV)
               | (k1.x != PADV) | (k1.y != PADV) | (k1.z != PADV) | (k1.w != PADV)
               | (k2.x != PADV) | (k2.y != PADV) | (k2.z != PADV) | (k2.w != PADV)
               | (k3.x != PADV) | (k3.y != PADV) | (k3.z != PADV) | (k3.w != PADV);
        ok = __any_sync(0xffffffffu, ok);
        if (lane == 0 && ok) atomicOr(&s_mask[(t - t0) >> 5], 1u << ((t - t0) & 31));
    }
    int eos_step = MAXLEN;

    grid_barrier();

    const float scale = 0.04419417382415922f;   // 1/sqrt(512)

    for (int k = 0; k <= MAXLEN; ++k) {
        // ============ Phase A: epilogue of step k-1 ============
        if (k > 0) {
            const int p  = (k - 1) % NBUF;
            const int pl = (k - 1) & 1;
            const float inv_total = 1.0f / g_tot[p];

            const int pg = k & 1;
            const float gh0 = g_gh[pg][0][tid];
            const float gh1 = g_gh[pg][1][tid];
            const float gh2 = g_gh[pg][2][tid];

            if (wid == 0) {
                float lg = -1e30f;
                if (lane < NVOCAB)
                    lg = g_ldot[p][lane * LDSTRIDE] * inv_total + g_lh[pl][lane];
                unsigned kb = __float_as_uint(lg);
                kb = (kb & 0x80000000u) ? ~kb : (kb | 0x80000000u);
                unsigned long long pk = ((unsigned long long)kb << 6) | (unsigned)(63 - lane);
                #pragma unroll
                for (int o = 16; o; o >>= 1) {
                    unsigned long long q = __shfl_xor_sync(0xffffffffu, pk, o);
                    if (q > pk) pk = q;
                }
                if (lane == 0) {
                    int best = 63 - (int)(pk & 63u);
                    s_best = best;
                    if (blk == 0 && best == EOSI && eos_step == MAXLEN) eos_step = k - 1;
                }
                if (blk == 0 && lane < NVOCAB)
                    out_logits[(k - 1) * NVOCAB + lane] = lg;
            } else if (wid == 1) {
                if (blk == 0) {
                    const int zb = (k + 1) % NBUF;
                    if (lane < NVOCAB) g_ldot[zb][lane * LDSTRIDE] = 0.0f;
                    if (lane == 31) g_tot[zb] = 0.0f;
                }
            } else {
                for (int t = t0 + (tid - 64); t < t1; t += NTHR - 64)
                    out_attn[(size_t)(k - 1) * TENC + t] = s_exp[t - t0] * inv_total;
            }
            __syncthreads();

            if (k == MAXLEN) break;

            const float* gx = g_gx[s_best];
            float r = 1.0f / (1.0f + __expf(-(gx[tid]           + gh0)));
            float z = 1.0f / (1.0f + __expf(-(gx[tid + HID]     + gh1)));
            float n = tanhf(gx[tid + 2 * HID] + r * gh2);
            s_hh[tid] = (1.0f - z) * n + z * s_hh[tid];
            __syncthreads();
        } else {
            const float* gx = g_gx[EOSI];
            float r = 1.0f / (1.0f + __expf(-(gx[tid]           + g_gh[0][0][tid])));
            float z = 1.0f / (1.0f + __expf(-(gx[tid + HID]     + g_gh[0][1][tid])));
            float n = tanhf(gx[tid + 2 * HID] + r * g_gh[0][2][tid]);
            s_hh[tid] = (1.0f - z) * n;
            __syncthreads();
        }

        // ============ Phase B: attention sweep (fp16 enc) ============
        float4 hA0 = *(const float4*)(s_hh + l8);
        float4 hA1 = *(const float4*)(s_hh + l8 + 4);
        float4 hB0 = *(const float4*)(s_hh + 256 + l8);
        float4 hB1 = *(const float4*)(s_hh + 256 + l8 + 4);
        float4 h0 = *(const float4*)(s_hh + base);
        float4 h1 = *(const float4*)(s_hh + base + 128);
        float4 h2 = *(const float4*)(s_hh + base + 256);
        float4 h3 = *(const float4*)(s_hh + base + 384);

        // lh duty: blocks 32..62, warp 0
        if (wid == 0 && blk >= 32 && blk < 32 + NVOCAB) {
            const int v = blk - 32;
            const float* wrow = w_out + (size_t)v * 1024 + HID;
            float dot = 0.0f;
            float4 w4;
            w4 = *(const float4*)(wrow + base);
            dot = fmaf(w4.x, h0.x, fmaf(w4.y, h0.y, fmaf(w4.z, h0.z, fmaf(w4.w, h0.w, dot))));
            w4 = *(const float4*)(wrow + base + 128);
            dot = fmaf(w4.x, h1.x, fmaf(w4.y, h1.y, fmaf(w4.z, h1.z, fmaf(w4.w, h1.w, dot))));
            w4 = *(const float4*)(wrow + base + 256);
            dot = fmaf(w4.x, h2.x, fmaf(w4.y, h2.y, fmaf(w4.z, h2.z, fmaf(w4.w, h2.w, dot))));
            w4 = *(const float4*)(wrow + base + 384);
            dot = fmaf(w4.x, h3.x, fmaf(w4.y, h3.y, fmaf(w4.z, h3.z, fmaf(w4.w, h3.w, dot))));
            dot = warp_allsum(dot);
            if (lane == 0) g_lh[k & 1][v] = dot + b_out[v];
        }

        float4 accA0 = {0,0,0,0}, accA1 = {0,0,0,0}, accB0 = {0,0,0,0}, accB1 = {0,0,0,0};
        float esum = 0.0f;

        // ---- streamed rows: software-pipelined, fp16, 4 LDG.128/row ----
        {
            uint4 kA, kB, vA, vB;
            int t = ts + wid;
            if (t < t1) {
                const uint4* row = (const uint4*)(g_enc16 + (size_t)t * 512);
                kA = __ldcg(row + lane);
                kB = __ldcg(row + 32 + lane);
                vA = __ldcg(row + 64 + lane);
                vB = __ldcg(row + 96 + lane);
            }
            for (; t < t1; t += NW) {
                const int tn = t + NW;
                const uint4* rn = (const uint4*)(g_enc16 + (size_t)((tn < t1) ? tn : t) * 512);
                uint4 nkA = __ldcg(rn + lane);
                uint4 nkB = __ldcg(rn + 32 + lane);
                uint4 nvA = __ldcg(rn + 64 + lane);
                uint4 nvB = __ldcg(rn + 96 + lane);

                float d0 = 0.0f, d1 = 0.0f;
                H2FMA(d0, kA.x, hA0.x, hA0.y); H2FMA(d1, kA.y, hA0.z, hA0.w);
                H2FMA(d0, kA.z, hA1.x, hA1.y); H2FMA(d1, kA.w, hA1.z, hA1.w);
                H2FMA(d0, kB.x, hB0.x, hB0.y); H2FMA(d1, kB.y, hB0.z, hB0.w);
                H2FMA(d0, kB.z, hB1.x, hB1.y); H2FMA(d1, kB.w, hB1.z, hB1.w);
                float d = d0 + d1;
                d = warp_allsum(d);
                const int it = t - t0;
                const unsigned m = (s_mask[it >> 5] >> (it & 31)) & 1u;
                float e = m ? __expf(d * scale) : 0.0f;
                if (lane == 0) { s_exp[it] = e; esum += e; }
                H2ACC(accA0.x, accA0.y, vA.x, e);
                H2ACC(accA0.z, accA0.w, vA.y, e);
                H2ACC(accA1.x, accA1.y, vA.z, e);
                H2ACC(accA1.z, accA1.w, vA.w, e);
                H2ACC(accB0.x, accB0.y, vB.x, e);
                H2ACC(accB0.z, accB0.w, vB.y, e);
                H2ACC(accB1.x, accB1.y, vB.z, e);
                H2ACC(accB1.z, accB1.w, vB.w, e);
                kA = nkA; kB = nkB; vA = nvA; vB = nvB;
            }
        }

        // ---- pinned rows (smem, fp16) ----
        for (int t = t0 + wid; t < ts; t += NW) {
            const uint4* row = (const uint4*)(s_enc16 + (size_t)(t - t0) * 512);
            uint4 kA = row[lane];
            uint4 kB = row[32 + lane];
            uint4 vA = row[64 + lane];
            uint4 vB = row[96 + lane];
            float d0 = 0.0f, d1 = 0.0f;
            H2FMA(d0, kA.x, hA0.x, hA0.y); H2FMA(d1, kA.y, hA0.z, hA0.w);
            H2FMA(d0, kA.z, hA1.x, hA1.y); H2FMA(d1, kA.w, hA1.z, hA1.w);
            H2FMA(d0, kB.x, hB0.x, hB0.y); H2FMA(d1, kB.y, hB0.z, hB0.w);
            H2FMA(d0, kB.z, hB1.x, hB1.y); H2FMA(d1, kB.w, hB1.z, hB1.w);
            float d = d0 + d1;
            d = warp_allsum(d);
            const int it = t - t0;
            const unsigned m = (s_mask[it >> 5] >> (it & 31)) & 1u;
            float e = m ? __expf(d * scale) : 0.0f;
            if (lane == 0) { s_exp[it] = e; esum += e; }
            H2ACC(accA0.x, accA0.y, vA.x, e);
            H2ACC(accA0.z, accA0.w, vA.y, e);
            H2ACC(accA1.x, accA1.y, vA.z, e);
            H2ACC(accA1.z, accA1.w, vA.w, e);
            H2ACC(accB0.x, accB0.y, vB.x, e);
            H2ACC(accB0.z, accB0.w, vB.y, e);
            H2ACC(accB1.x, accB1.y, vB.z, e);
            H2ACC(accB1.z, accB1.w, vB.w, e);
        }

        // gh duty: blocks 32..127, one dot per warp (fp32)
        if (blk >= 32 && blk < 128) {
            const int d  = (blk - 32) * NW + wid;
            const int g  = d >> 9;
            const int j  = d & 511;
            const int pn = (k + 1) & 1;
            const float* ur = w_hh + (size_t)(g * HID + j) * HID;
            float a = 0.0f;
            #pragma unroll
            for (int m = 0; m < 4; ++m) {
                int c = base + m * 128;
                float4 hx = *(const float4*)(s_hh + c);
                float4 u4 = *(const float4*)(ur + c);
                a = fmaf(hx.x, u4.x, fmaf(hx.y, u4.y, fmaf(hx.z, u4.z, fmaf(hx.w, u4.w, a))));
            }
            a = warp_allsum(a);
            if (lane == 0) g_gh[pn][g][j] = a + b_hh[g * HID + j];
        }

        // ---- merge: two-phase staging (fp16 lane layout) ----
        if (lane == 0) s_red[wid] = esum;
        if (wid < 8) {
            *(float4*)&s_warp[wid][l8]           = accA0;
            *(float4*)&s_warp[wid][l8 + 4]       = accA1;
            *(float4*)&s_warp[wid][256 + l8]     = accB0;
            *(float4*)&s_warp[wid][256 + l8 + 4] = accB1;
        }
        __syncthreads();
        if (wid >= 8) {
            float* bdst = s_warp[wid - 8];
            float4 t;
            t = *(float4*)&bdst[l8];
            t.x += accA0.x; t.y += accA0.y; t.z += accA0.z; t.w += accA0.w;
            *(float4*)&bdst[l8] = t;
            t = *(float4*)&bdst[l8 + 4];
            t.x += accA1.x; t.y += accA1.y; t.z += accA1.z; t.w += accA1.w;
            *(float4*)&bdst[l8 + 4] = t;
            t = *(float4*)&bdst[256 + l8];
            t.x += accB0.x; t.y += accB0.y; t.z += accB0.z; t.w += accB0.w;
            *(float4*)&bdst[256 + l8] = t;
            t = *(float4*)&bdst[256 + l8 + 4];
            t.x += accB1.x; t.y += accB1.y; t.z += accB1.z; t.w += accB1.w;
            *(float4*)&bdst[256 + l8 + 4] = t;
        }
        __syncthreads();
        {
            float colsum = 0.0f;
            #pragma unroll
            for (int w8 = 0; w8 < 8; ++w8) colsum += s_warp[w8][tid];
            s_sum[tid] = colsum;
        }
        __syncthreads();

        // ---- partial logit dots (fp32) ----
        const int bb = k % NBUF;
        for (int v = wid; v < NVOCAB; v += NW) {
            const float* wrow = s_woutS + v * HID;
            float dot = 0.0f;
            #pragma unroll
            for (int m = 0; m < 4; ++m) {
                int c = base + m * 128;
                float4 w4 = *(const float4*)(wrow + c);
                float4 x4 = *(const float4*)(s_sum + c);
                dot = fmaf(w4.x, x4.x, fmaf(w4.y, x4.y, fmaf(w4.z, x4.z, fmaf(w4.w, x4.w, dot))));
            }
            dot = warp_allsum(dot);
            if (lane == 0) atomicAdd(&g_ldot[bb][v * LDSTRIDE], dot);
        }
        if (tid == 0) {
            float tot = 0.0f;
            #pragma unroll
            for (int w8 = 0; w8 < NW; ++w8) tot += s_red[w8];
            atomicAdd(&g_tot[bb], tot);
        }

        grid_barrier();
    }

    if (blk == 0 && tid == 0) out_len[0] = (float)eos_step;
}

extern "C" void kernel_launch(void* const* d_in, const int* in_sizes, int n_in,
                              void* d_out, int out_size) {
    const float* enc   = (const float*)d_in[0];
    const float* embed = (const float*)d_in[2];
    const float* w_ih  = (const float*)d_in[3];
    const float* w_hh  = (const float*)d_in[4];
    const float* b_ih  = (const float*)d_in[5];
    const float* b_hh  = (const float*)d_in[6];
    const float* w_out = (const float*)d_in[7];
    const float* b_out = (const float*)d_in[8];
    (void)in_sizes; (void)n_in; (void)out_size;

    const int smem_dyn = (PCACHE * 512 + NVOCAB * HID) * sizeof(float);   // 161792 B
    static int nblk = 0;
    if (!nblk) {
        cudaFuncSetAttribute(decoder_kernel,
                             cudaFuncAttributeMaxDynamicSharedMemorySize, smem_dyn);
        int dev = 0;
        cudaGetDevice(&dev);
        int sms = 0;
        cudaDeviceGetAttribute(&sms, cudaDevAttrMultiProcessorCount, dev);
        nblk = (sms >= 128 && sms <= MAXBLK) ? sms : 148;
    }
    decoder_kernel<<<nblk, NTHR, smem_dyn>>>(enc, embed, w_ih, w_hh, b_ih, b_hh,
                                             w_out, b_out, (float*)d_out);
}